// round 14
// baseline (speedup 1.0000x reference)
#include <cuda_runtime.h>

#define T_STEPS 96
#define BATCH   128
#define FILTER_BLOCKS 64
#define WRITER_BLOCKS 84

// Output section offsets (floats), tuple order:
// mu_filt, sigma_filt, mu_pred, sigma_pred, latent_means, latent_variances, S
#define OFF_MUF   0
#define OFF_SIGF  393216
#define OFF_MUP   12976128
#define OFF_SIGP  13369344
#define OFF_LM    25952256
#define OFF_LV    26738688
#define OFF_S     51904512

#define PZ 36   // 32-wide rows padded: 144B, 16B-aligned
#define PA 20   // 16-wide rows padded: 80B, 16B-aligned

typedef unsigned long long u64;

__device__ __forceinline__ void dfma(u64& acc, u64 a, u64 b) {
    asm("fma.rn.f32x2 %0, %1, %2, %0;" : "+l"(acc) : "l"(a), "l"(b));
}
__device__ __forceinline__ float dsum(u64 a) {
    unsigned lo, hi;
    asm("mov.b64 {%0, %1}, %2;" : "=r"(lo), "=r"(hi) : "l"(a));
    return __uint_as_float(lo) + __uint_as_float(hi);
}

struct SmemHalf {
    float sigB[2][32][PZ];
    float Ush [32][PZ];
    float Rsh [32][PZ];
    float Am  [32][PZ];
    float Dm  [32][PZ];
    float Ct  [16][PZ];
    float CSr [16][PZ];
    float CSc [32][PA];
    float Vsh [32][PA];
    float Gsh [32][PA];
    float Ksh [32][PA];
    float Sinv[16][PA];
    float Ssh [16][PA];
    float muB [2][32];
    float amv[32], dchv[32], rv[16], ov[16];
    float chain[24][32];
};

#define HBAR() asm volatile("bar.sync %0, %1;" :: "r"(1 + h), "r"(128) : "memory")

__global__ __launch_bounds__(256, 1)
void kalman_kernel(const float* __restrict__ obs,
                   const float* __restrict__ Ag_all,
                   const float* __restrict__ Cg_all,
                   const float* __restrict__ Dg_all,
                   float* __restrict__ out)
{
    const int tid = threadIdx.x;

    // ---------------- writer blocks: latent_variances (input-independent) ----
    if (blockIdx.x >= FILTER_BLOCKS) {
        float* out_lv = out + OFF_LV;
        int wb = blockIdx.x - FILTER_BLOCKS;          // 0..83
        for (int t = 0; t < T_STEPS; ++t) {
            float d0 = (t >= 2) ? 0.08f : 0.f;
            float d1 = (t <  4) ? 20.f  : 0.f;
            float4* dst = (float4*)(out_lv + (size_t)t * BATCH * 2048);
            for (int e4 = wb * 256 + tid; e4 < 65536; e4 += WRITER_BLOCKS * 256) {
                int v2 = (e4 * 4) & 2047;
                int l  = v2 >> 10;
                int ij = v2 & 1023;
                int i  = ij >> 5, j0 = ij & 31;
                float dv = l ? d1 : d0;
                bool hit = ((i >> 2) == (j0 >> 2));
                float4 v;
                v.x = (hit && (i & 3) == 0) ? dv : 0.f;
                v.y = (hit && (i & 3) == 1) ? dv : 0.f;
                v.z = (hit && (i & 3) == 2) ? dv : 0.f;
                v.w = (hit && (i & 3) == 3) ? dv : 0.f;
                dst[e4] = v;
            }
        }
        return;
    }

    extern __shared__ char smraw[];
    SmemHalf* smh = (SmemHalf*)smraw;

    const int h    = tid >> 7;             // half 0/1
    const int tid2 = tid & 127;
    const int lane = tid & 31;
    const int w2   = (tid2 >> 5);          // warp in half, 0..3
    const int b    = blockIdx.x * 2 + h;   // batch index

    SmemHalf& sh = smh[h];

    float* out_muf  = out + OFF_MUF;
    float* out_sigf = out + OFF_SIGF;
    float* out_mup  = out + OFF_MUP;
    float* out_sigp = out + OFF_SIGP;
    float* out_lm   = out + OFF_LM;
    float* out_S    = out + OFF_S;

    // ---------------- Prologue: top-level latent chain (block-wide) --------
    if (tid2 < 32) sh.chain[0][tid2] = 0.01f;
    {
        float4 pf[2][2];
        #pragma unroll
        for (int s = 0; s < 2; ++s) {
            const float* Ag = Ag_all + ((size_t)(b * T_STEPS + 4 * (s + 1)) * 3 + 2) * 1024;
            pf[s][0] = *(const float4*)(Ag + (tid2 * 2 + 0) * 4);
            pf[s][1] = *(const float4*)(Ag + (tid2 * 2 + 1) * 4);
        }
        __syncthreads();
        for (int j = 1; j <= 23; ++j) {
            int s = (j - 1) & 1;
            #pragma unroll
            for (int k = 0; k < 2; ++k) {
                int e4 = tid2 * 2 + k;
                *(float4*)&sh.Am[e4 >> 3][(e4 & 7) * 4] = pf[s][k];
            }
            if (j + 2 <= 23) {
                const float* Ag = Ag_all + ((size_t)(b * T_STEPS + 4 * (j + 2)) * 3 + 2) * 1024;
                pf[s][0] = *(const float4*)(Ag + (tid2 * 2 + 0) * 4);
                pf[s][1] = *(const float4*)(Ag + (tid2 * 2 + 1) * 4);
            }
            __syncthreads();
            if (tid2 < 32) {
                const ulonglong2* ar = (const ulonglong2*)&sh.Am[tid2][0];
                const ulonglong2* ch = (const ulonglong2*)&sh.chain[j - 1][0];
                u64 acc = 0;
                #pragma unroll
                for (int q = 0; q < 8; ++q) {
                    dfma(acc, ar[q].x, ch[q].x);
                    dfma(acc, ar[q].y, ch[q].y);
                }
                sh.chain[j][tid2] = dsum(acc);
            }
            __syncthreads();
        }
    }

    // ---------------- init state + t=0 prior outputs + step-0/1 operands ----
    float4 rA[2], rD[2], rC = make_float4(0, 0, 0, 0);
    float  rO = 0.f;
    {
        *(float4*)&sh.Ct[tid2 >> 3][(tid2 & 7) * 4] =
            *(const float4*)(Cg_all + (size_t)(b * T_STEPS) * 512 + tid2 * 4);
        if (tid2 < 16) sh.ov[tid2] = obs[(size_t)b * 16 + tid2];
        #pragma unroll
        for (int k = 0; k < 2; ++k) {
            int e4 = tid2 * 2 + k;
            int row = e4 >> 3, c0 = (e4 & 7) * 4;
            float4 sv = make_float4(0, 0, 0, 0);
            if (row >= c0 && row < c0 + 4) {
                int d = row - c0;
                sv.x = (d == 0) ? 20.f : 0.f;
                sv.y = (d == 1) ? 20.f : 0.f;
                sv.z = (d == 2) ? 20.f : 0.f;
                sv.w = (d == 3) ? 20.f : 0.f;
            }
            *(float4*)&sh.sigB[0][row][c0] = sv;
            *(float4*)(out_sigp + (size_t)b * 1024 + e4 * 4) = sv;
        }
        if (tid2 < 32) sh.muB[0][tid2] = 0.f;
        if (tid2 < 8)
            *(float4*)(out_mup + (size_t)b * 32 + tid2 * 4) = make_float4(0, 0, 0, 0);
        const float* Ag = Ag_all + (size_t)(b * T_STEPS + 1) * 3 * 1024;
        const float* Dg = Dg_all + (size_t)(b * T_STEPS + 1) * 2 * 1024;
        #pragma unroll
        for (int k = 0; k < 2; ++k) {
            rA[k] = *(const float4*)(Ag + (tid2 * 2 + k) * 4);
            rD[k] = *(const float4*)(Dg + (tid2 * 2 + k) * 4);
        }
    }
    __syncthreads();

    // ---------------- main sequential filter (per-half barriers) ----------
    for (int t = 0; t < T_STEPS; ++t) {
        const size_t tb = (size_t)t * BATCH + b;
        float (*sgc)[PZ] = sh.sigB[t & 1];
        float (*sgn)[PZ] = sh.sigB[(t + 1) & 1];
        float* muc = sh.muB[t & 1];
        float* mun = sh.muB[(t + 1) & 1];
        const bool more = (t + 1 < T_STEPS);

        ulonglong2 scol[8];   // sigma column `lane`

        // ---- P1: stage A/D; prefetch; CS = C@sigma (4 rows/warp); r; S ----
        {
            #pragma unroll
            for (int k = 0; k < 2; ++k) {
                int e4 = tid2 * 2 + k;
                *(float4*)&sh.Am[e4 >> 3][(e4 & 7) * 4] = rA[k];
                *(float4*)&sh.Dm[e4 >> 3][(e4 & 7) * 4] = rD[k];
            }
            if (t + 2 < T_STEPS) {
                const float* Ag = Ag_all + (size_t)(b * T_STEPS + t + 2) * 3 * 1024;
                const float* Dg = Dg_all + (size_t)(b * T_STEPS + t + 2) * 2 * 1024;
                #pragma unroll
                for (int k = 0; k < 2; ++k) {
                    rA[k] = *(const float4*)(Ag + (tid2 * 2 + k) * 4);
                    rD[k] = *(const float4*)(Dg + (tid2 * 2 + k) * 4);
                }
            }
            if (more) {
                rC = *(const float4*)(Cg_all + (size_t)(b * T_STEPS + t + 1) * 512 + tid2 * 4);
                if (tid2 < 16)
                    rO = obs[(size_t)((t + 1) * BATCH + b) * 16 + tid2];
            }
            const ulonglong2* sc = (const ulonglong2*)&sgc[lane][0];
            #pragma unroll
            for (int q = 0; q < 8; ++q) scol[q] = sc[q];
            #pragma unroll
            for (int a = 0; a < 4; ++a) {
                int row = w2 + 4 * a;
                const ulonglong2* cr = (const ulonglong2*)&sh.Ct[row][0];
                u64 acc = 0;
                #pragma unroll
                for (int q = 0; q < 8; ++q) {
                    dfma(acc, cr[q].x, scol[q].x);
                    dfma(acc, cr[q].y, scol[q].y);
                }
                float s = dsum(acc);
                sh.CSr[row][lane] = s;
                sh.CSc[lane][row] = s;
            }
            if (tid2 < 16) {
                const ulonglong2* c4 = (const ulonglong2*)&sh.Ct[tid2][0];
                const ulonglong2* m4 = (const ulonglong2*)muc;
                u64 acc = 0;
                #pragma unroll
                for (int q = 0; q < 8; ++q) {
                    dfma(acc, c4[q].x, m4[q].x);
                    dfma(acc, c4[q].y, m4[q].y);
                }
                sh.rv[tid2] = sh.ov[tid2] - dsum(acc);
            }
            __syncwarp();
            // S: warp-local rows {w2+4a}; thread does a = lane>>4 and a+2
            #pragma unroll
            for (int p = 0; p < 2; ++p) {
                int a2  = (lane >> 4) + 2 * p;
                int row = w2 + 4 * a2;
                int j   = lane & 15;
                const ulonglong2* a4 = (const ulonglong2*)&sh.CSr[row][0];
                const ulonglong2* c4 = (const ulonglong2*)&sh.Ct[j][0];
                u64 acc = 0;
                #pragma unroll
                for (int q = 0; q < 8; ++q) {
                    dfma(acc, a4[q].x, c4[q].x);
                    dfma(acc, a4[q].y, c4[q].y);
                }
                float s = ((row == j) ? 0.03f : 0.f) + dsum(acc);
                sh.Ssh[row][j] = s;
                out_S[tb * 256 + row * 16 + j] = s;
            }
        }
        HBAR();

        // ---- P3: warp0 GJ inverse; warps 1-3: U, V, Amu, Dch, R20, lm ----
        if (w2 == 0) {
            const int lrow = lane & 15;
            float M[16];
            const float4* sr = (const float4*)&sh.Ssh[lrow][0];
            #pragma unroll
            for (int q = 0; q < 4; ++q) {
                float4 v = sr[q];
                M[4 * q + 0] = v.x; M[4 * q + 1] = v.y;
                M[4 * q + 2] = v.z; M[4 * q + 3] = v.w;
            }
            #pragma unroll
            for (int j = 0; j < 16; ++j) {
                float pj = __shfl_sync(0xffffffffu, M[j], j);
                float ip;
                asm("rcp.approx.ftz.f32 %0, %1;" : "=f"(ip) : "f"(pj));
                float f  = M[j];
                bool isj = (lrow == j);
                #pragma unroll
                for (int kk = 1; kk < 16; ++kk) {
                    int k = (j + kk) & 15;
                    float rj = __shfl_sync(0xffffffffu, M[k], j);
                    float v  = rj * ip;
                    M[k] = isj ? v : fmaf(-f, v, M[k]);
                }
                M[j] = isj ? ip : (-f * ip);
            }
            if (lane < 16) {
                float4* dst = (float4*)&sh.Sinv[lane][0];
                #pragma unroll
                for (int q = 0; q < 4; ++q)
                    dst[q] = make_float4(M[4 * q], M[4 * q + 1], M[4 * q + 2], M[4 * q + 3]);
            }
        } else {
            if (w2 == 1 && lane < 16) {
                float4 v = make_float4(0, 0, 0, 0);
                if (lane >= 8) v = *(const float4*)&sh.chain[t >> 2][(lane - 8) * 4];
                *(float4*)(out_lm + tb * 64 + lane * 4) = v;
            }
            if (more) {
                ulonglong2 wr[8];
                #pragma unroll
                for (int q = 0; q < 8; ++q)
                    wr[q] = ((const ulonglong2*)&sh.CSr[lane & 15][0])[q];
                #pragma unroll
                for (int m = 0; m < 11; ++m) {
                    int r = (w2 - 1) + 3 * m;
                    if (r < 32) {
                        const ulonglong2* ar = (const ulonglong2*)&sh.Am[r][0];
                        u64 ua = 0, va = 0;
                        #pragma unroll
                        for (int q = 0; q < 8; ++q) {
                            ulonglong2 a = ar[q];
                            dfma(ua, a.x, scol[q].x);  dfma(ua, a.y, scol[q].y);
                            dfma(va, a.x, wr[q].x);    dfma(va, a.y, wr[q].y);
                        }
                        sh.Ush[r][lane] = dsum(ua);
                        sh.Vsh[r][lane & 15] = dsum(va);
                    }
                }
                if (w2 == 3) {   // Amu + Dch
                    const ulonglong2* al7 = (const ulonglong2*)&sh.Am[lane][0];
                    const ulonglong2* dl7 = (const ulonglong2*)&sh.Dm[lane][0];
                    const ulonglong2* m4  = (const ulonglong2*)muc;
                    const ulonglong2* ch  = (const ulonglong2*)&sh.chain[t >> 2][0];
                    u64 am = 0, dc = 0;
                    #pragma unroll
                    for (int q = 0; q < 8; ++q) {
                        dfma(am, al7[q].x, m4[q].x);  dfma(am, al7[q].y, m4[q].y);
                        dfma(dc, dl7[q].x, ch[q].x);  dfma(dc, dl7[q].y, ch[q].y);
                    }
                    sh.amv[lane]  = dsum(am);
                    sh.dchv[lane] = dsum(dc);
                }
                if (t < 4) {     // R20 = 20 * D @ D^T
                    ulonglong2 dcol[8];
                    #pragma unroll
                    for (int q = 0; q < 8; ++q)
                        dcol[q] = ((const ulonglong2*)&sh.Dm[lane][0])[q];
                    #pragma unroll
                    for (int m = 0; m < 11; ++m) {
                        int r = (w2 - 1) + 3 * m;
                        if (r < 32) {
                            const ulonglong2* dr = (const ulonglong2*)&sh.Dm[r][0];
                            u64 acc = 0;
                            #pragma unroll
                            for (int q = 0; q < 8; ++q) {
                                dfma(acc, dr[q].x, dcol[q].x);
                                dfma(acc, dr[q].y, dcol[q].y);
                            }
                            sh.Rsh[r][lane] = 20.f * dsum(acc);
                        }
                    }
                }
            }
        }
        HBAR();

        // ---- P4: K/G cols {w2+4a} of row `lane`; al; t1 a=0..3; stage C ----
        ulonglong2 al[8];
        ulonglong2 wl[4];
        ulonglong2 vl[4];
        float t1v[8];
        {
            #pragma unroll
            for (int q = 0; q < 4; ++q) wl[q] = ((const ulonglong2*)&sh.CSc[lane][0])[q];
            #pragma unroll
            for (int a = 0; a < 4; ++a) {
                int c = w2 + 4 * a;
                const ulonglong2* si = (const ulonglong2*)&sh.Sinv[c][0];
                u64 acc = 0;
                #pragma unroll
                for (int q = 0; q < 4; ++q) {
                    dfma(acc, wl[q].x, si[q].x);
                    dfma(acc, wl[q].y, si[q].y);
                }
                sh.Ksh[lane][c] = dsum(acc);
            }
            if (more) {
                #pragma unroll
                for (int q = 0; q < 4; ++q) vl[q] = ((const ulonglong2*)&sh.Vsh[lane][0])[q];
                #pragma unroll
                for (int a = 0; a < 4; ++a) {
                    int c = w2 + 4 * a;
                    const ulonglong2* si = (const ulonglong2*)&sh.Sinv[c][0];
                    u64 acc = 0;
                    #pragma unroll
                    for (int q = 0; q < 4; ++q) {
                        dfma(acc, vl[q].x, si[q].x);
                        dfma(acc, vl[q].y, si[q].y);
                    }
                    sh.Gsh[lane][c] = dsum(acc);
                }
                #pragma unroll
                for (int q = 0; q < 8; ++q) al[q] = ((const ulonglong2*)&sh.Am[lane][0])[q];
                #pragma unroll
                for (int a = 0; a < 4; ++a) {
                    int r = w2 + 4 * a;
                    const ulonglong2* ur = (const ulonglong2*)&sh.Ush[r][0];
                    u64 acc = 0;
                    #pragma unroll
                    for (int q = 0; q < 8; ++q) {
                        dfma(acc, ur[q].x, al[q].x);
                        dfma(acc, ur[q].y, al[q].y);
                    }
                    t1v[a] = dsum(acc);
                }
                *(float4*)&sh.Ct[tid2 >> 3][(tid2 & 7) * 4] = rC;
                if (tid2 < 16) sh.ov[tid2] = rO;
            }
        }
        HBAR();

        // ---- P5: sigf rows {w2+4a}; sigma' = t1 - G V^T + Q (+R20); mu' ----
        {
            #pragma unroll
            for (int a = 0; a < 8; ++a) {
                int r = w2 + 4 * a;
                const ulonglong2* kr = (const ulonglong2*)&sh.Ksh[r][0];
                u64 acc = 0;
                #pragma unroll
                for (int q = 0; q < 4; ++q) {
                    dfma(acc, kr[q].x, wl[q].x);
                    dfma(acc, kr[q].y, wl[q].y);
                }
                out_sigf[tb * 1024 + r * 32 + lane] = sgc[r][lane] - dsum(acc);
            }
            if (tid2 < 32) {   // mu_filt
                const ulonglong2* kk = (const ulonglong2*)&sh.Ksh[tid2][0];
                const ulonglong2* r4 = (const ulonglong2*)sh.rv;
                u64 acc = 0;
                #pragma unroll
                for (int q = 0; q < 4; ++q) {
                    dfma(acc, kk[q].x, r4[q].x);
                    dfma(acc, kk[q].y, r4[q].y);
                }
                out_muf[tb * 32 + tid2] = muc[tid2] + dsum(acc);
            }
            if (more) {
                const size_t tb2 = tb + BATCH;
                #pragma unroll
                for (int a = 4; a < 8; ++a) {
                    int r = w2 + 4 * a;
                    const ulonglong2* ur = (const ulonglong2*)&sh.Ush[r][0];
                    u64 acc = 0;
                    #pragma unroll
                    for (int q = 0; q < 8; ++q) {
                        dfma(acc, ur[q].x, al[q].x);
                        dfma(acc, ur[q].y, al[q].y);
                    }
                    t1v[a] = dsum(acc);
                }
                #pragma unroll
                for (int a = 0; a < 8; ++a) {
                    int r = w2 + 4 * a;
                    const ulonglong2* gr = (const ulonglong2*)&sh.Gsh[r][0];
                    u64 acc = 0;
                    #pragma unroll
                    for (int q = 0; q < 4; ++q) {
                        dfma(acc, gr[q].x, vl[q].x);
                        dfma(acc, gr[q].y, vl[q].y);
                    }
                    float s = t1v[a] - dsum(acc);
                    if (r == lane) s += 0.08f;
                    if (t < 4)     s += sh.Rsh[r][lane];
                    sgn[r][lane] = s;
                    out_sigp[tb2 * 1024 + r * 32 + lane] = s;
                }
                if (w2 == 1) {   // mu' = Amu + G r + Dch
                    const ulonglong2* gr = (const ulonglong2*)&sh.Gsh[lane][0];
                    const ulonglong2* r4 = (const ulonglong2*)sh.rv;
                    u64 acc = 0;
                    #pragma unroll
                    for (int q = 0; q < 4; ++q) {
                        dfma(acc, gr[q].x, r4[q].x);
                        dfma(acc, gr[q].y, r4[q].y);
                    }
                    float m = sh.amv[lane] + sh.dchv[lane] + dsum(acc);
                    mun[lane] = m;
                    out_mup[tb2 * 32 + lane] = m;
                }
            }
        }
        HBAR();
    }
}

extern "C" void kernel_launch(void* const* d_in, const int* in_sizes, int n_in,
                              void* d_out, int out_size) {
    const float* obs = (const float*)d_in[0];
    const float* A   = (const float*)d_in[1];
    const float* C   = (const float*)d_in[2];
    const float* D   = (const float*)d_in[3];
    int smem = (int)(2 * sizeof(SmemHalf));
    cudaFuncSetAttribute(kalman_kernel,
                         cudaFuncAttributeMaxDynamicSharedMemorySize, smem);
    kalman_kernel<<<FILTER_BLOCKS + WRITER_BLOCKS, 256, smem>>>(
        obs, A, C, D, (float*)d_out);
}

// round 15
// speedup vs baseline: 1.3323x; 1.3323x over previous
#include <cuda_runtime.h>

#define T_STEPS 96
#define BATCH   128

// Output section offsets (floats), tuple order:
// mu_filt, sigma_filt, mu_pred, sigma_pred, latent_means, latent_variances, S
#define OFF_MUF   0
#define OFF_SIGF  393216
#define OFF_MUP   12976128
#define OFF_SIGP  13369344
#define OFF_LM    25952256
#define OFF_LV    26738688
#define OFF_S     51904512

#define PZ 36   // 32-wide rows padded: 144B, 16B-aligned
#define PA 20   // 16-wide rows padded: 80B, 16B-aligned

typedef unsigned long long u64;

// packed f32x2 fused multiply-add: acc.{lo,hi} += a.{lo,hi} * b.{lo,hi}
__device__ __forceinline__ void dfma(u64& acc, u64 a, u64 b) {
    asm("fma.rn.f32x2 %0, %1, %2, %0;" : "+l"(acc) : "l"(a), "l"(b));
}
__device__ __forceinline__ float dsum(u64 a) {
    unsigned lo, hi;
    asm("mov.b64 {%0, %1}, %2;" : "=r"(lo), "=r"(hi) : "l"(a));
    return __uint_as_float(lo) + __uint_as_float(hi);
}

__global__ __launch_bounds__(256, 1)
void kalman_kernel(const float* __restrict__ obs,
                   const float* __restrict__ Ag_all,
                   const float* __restrict__ Cg_all,
                   const float* __restrict__ Dg_all,
                   float* __restrict__ out)
{
    const int tid  = threadIdx.x;

    // ---------------- writer blocks: latent_variances (input-independent) ----
    if (blockIdx.x >= BATCH) {
        float* out_lv = out + OFF_LV;
        int wb = blockIdx.x - BATCH;          // 0..19
        for (int t = 0; t < T_STEPS; ++t) {
            float d0 = (t >= 2) ? 0.08f : 0.f;
            float d1 = (t <  4) ? 20.f  : 0.f;
            float4* dst = (float4*)(out_lv + (size_t)t * BATCH * 2048);
            for (int e4 = wb * 256 + tid; e4 < 65536; e4 += 20 * 256) {
                int v2 = (e4 * 4) & 2047;
                int l  = v2 >> 10;
                int ij = v2 & 1023;
                int i  = ij >> 5, j0 = ij & 31;
                float dv = l ? d1 : d0;
                bool hit = ((i >> 2) == (j0 >> 2));
                float4 v;
                v.x = (hit && (i & 3) == 0) ? dv : 0.f;
                v.y = (hit && (i & 3) == 1) ? dv : 0.f;
                v.z = (hit && (i & 3) == 2) ? dv : 0.f;
                v.w = (hit && (i & 3) == 3) ? dv : 0.f;
                dst[e4] = v;
            }
        }
        return;
    }

    const int b    = blockIdx.x;
    const int lane = tid & 31;
    const int wid  = tid >> 5;       // 0..7

    __shared__ __align__(16) float sigB[2][32][PZ]; // sigma ping-pong (symmetric)
    __shared__ __align__(16) float Ush [32][PZ];    // U = A @ sigma
    __shared__ __align__(16) float Rsh [32][PZ];    // 20*D@D^T (t<4)
    __shared__ __align__(16) float Am  [32][PZ];    // A[b,t+1,0]
    __shared__ __align__(16) float Dm  [32][PZ];    // D[b,t+1,0]
    __shared__ __align__(16) float A2sh[32][PZ];    // A[b,4j,2] for lazy chain
    __shared__ __align__(16) float Ct  [16][PZ];    // C[b,t]
    __shared__ __align__(16) float CSr [16][PZ];    // CS = C@sigma, row-major
    __shared__ __align__(16) float CSc [32][PA];    // W = sigma C^T (rows = z)
    __shared__ __align__(16) float Vsh [32][PA];    // V = A @ W
    __shared__ __align__(16) float Gsh [32][PA];    // G = V @ Sinv
    __shared__ __align__(16) float Ksh [32][PA];    // K = W @ Sinv
    __shared__ __align__(16) float Sinv[16][PA];
    __shared__ __align__(16) float Ssh [16][PA];
    __shared__ __align__(16) float muB[2][32];
    __shared__ __align__(16) float amv[32], dchv[32], rv[16], ov[16];
    __shared__ __align__(16) float chain[24][32];

    float* out_muf  = out + OFF_MUF;
    float* out_sigf = out + OFF_SIGF;
    float* out_mup  = out + OFF_MUP;
    float* out_sigp = out + OFF_SIGP;
    float* out_lm   = out + OFF_LM;
    float* out_S    = out + OFF_S;

    // ---------------- init state + t=0 prior outputs + step-0/1 operands ----
    float4 rA, rD, rC = make_float4(0, 0, 0, 0);
    float4 rA2 = make_float4(0, 0, 0, 0);
    float  rO = 0.f;
    if (tid < 32) chain[0][tid] = 0.01f;   // chain[j>=1] computed lazily in-loop
    {
        if (tid < 128)
            *(float4*)&Ct[tid >> 3][(tid & 7) * 4] =
                *(const float4*)(Cg_all + (size_t)(b * T_STEPS) * 512 + tid * 4);
        if (tid < 16) ov[tid] = obs[(size_t)b * 16 + tid];
        {
            int row = tid >> 3, c0 = (tid & 7) * 4;
            float4 sv = make_float4(0, 0, 0, 0);
            if (row >= c0 && row < c0 + 4) {
                int d = row - c0;
                sv.x = (d == 0) ? 20.f : 0.f;
                sv.y = (d == 1) ? 20.f : 0.f;
                sv.z = (d == 2) ? 20.f : 0.f;
                sv.w = (d == 3) ? 20.f : 0.f;
            }
            *(float4*)&sigB[0][row][c0] = sv;
            *(float4*)(out_sigp + (size_t)b * 1024 + tid * 4) = sv;
        }
        if (tid < 32) muB[0][tid] = 0.f;
        if (tid < 8)
            *(float4*)(out_mup + (size_t)b * 32 + tid * 4) = make_float4(0, 0, 0, 0);
        rA = *(const float4*)(Ag_all + (size_t)(b * T_STEPS + 1) * 3 * 1024 + tid * 4);
        rD = *(const float4*)(Dg_all + (size_t)(b * T_STEPS + 1) * 2 * 1024 + tid * 4);
    }
    __syncthreads();

    // ---------------- main sequential filter ----------------
    for (int t = 0; t < T_STEPS; ++t) {
        const size_t tb = (size_t)t * BATCH + b;
        float (*sgc)[PZ] = sigB[t & 1];
        float (*sgn)[PZ] = sigB[(t + 1) & 1];
        float* muc = muB[t & 1];
        float* mun = muB[(t + 1) & 1];

        ulonglong2 scol[8];   // register-cached sigma column `lane` (reused in P3)
        float sig_il[4];      // sgc[wid+8ii][lane] via symmetry (used in P5)

        // ---- P1: STS A/D[t+1] (+A2 lazy-chain staging); prefetch;
        //      CS = C@sigma; r = o - C@mu ----
        {
            int ar2 = tid >> 3, ac = (tid & 7) * 4;
            *(float4*)&Am[ar2][ac] = rA;
            *(float4*)&Dm[ar2][ac] = rD;
            if (t + 2 < T_STEPS) {
                rA = *(const float4*)(Ag_all + (size_t)(b * T_STEPS + t + 2) * 3 * 1024 + tid * 4);
                rD = *(const float4*)(Dg_all + (size_t)(b * T_STEPS + t + 2) * 2 * 1024 + tid * 4);
            }
            // lazy chain: prefetch A[b, t+4, 2] at t%4==0; stage at t%4==1
            if ((t & 3) == 0 && t <= 88) {
                rA2 = *(const float4*)(Ag_all +
                        ((size_t)(b * T_STEPS + t + 4) * 3 + 2) * 1024 + tid * 4);
            }
            if ((t & 3) == 1 && t <= 89) {
                *(float4*)&A2sh[ar2][ac] = rA2;
            }
            if (t + 1 < T_STEPS) {
                if (tid < 128)
                    rC = *(const float4*)(Cg_all + (size_t)(b * T_STEPS + t + 1) * 512 + tid * 4);
                if (tid < 16)
                    rO = obs[(size_t)((t + 1) * BATCH + b) * 16 + tid];
            }
            const ulonglong2* sc = (const ulonglong2*)&sgc[lane][0];
            const ulonglong2* c0 = (const ulonglong2*)&Ct[wid][0];
            const ulonglong2* c1 = (const ulonglong2*)&Ct[wid + 8][0];
            u64 a0 = 0, a1 = 0;
            #pragma unroll
            for (int q = 0; q < 8; ++q) {
                ulonglong2 g = sc[q];
                scol[q] = g;
                ulonglong2 x0 = c0[q], x1 = c1[q];
                dfma(a0, x0.x, g.x);  dfma(a0, x0.y, g.y);
                dfma(a1, x1.x, g.x);  dfma(a1, x1.y, g.y);
            }
            float s0 = dsum(a0), s1 = dsum(a1);
            CSr[wid][lane] = s0;      CSr[wid + 8][lane] = s1;
            CSc[lane][wid] = s0;      CSc[lane][wid + 8] = s1;
            // sig_il[ii] = sgc[wid+8ii][lane] == sgc[lane][wid+8ii] (symmetry)
            #pragma unroll
            for (int ii = 0; ii < 4; ++ii) {
                ulonglong2 sq = scol[2 * ii + (wid >> 2)];
                u64 part = (wid & 2) ? sq.y : sq.x;
                unsigned lo, hi;
                asm("mov.b64 {%0, %1}, %2;" : "=r"(lo), "=r"(hi) : "l"(part));
                sig_il[ii] = __uint_as_float((wid & 1) ? hi : lo);
            }
            if (tid < 16) {
                const ulonglong2* c4 = (const ulonglong2*)&Ct[tid][0];
                const ulonglong2* m4 = (const ulonglong2*)muc;
                u64 acc = 0;
                #pragma unroll
                for (int q = 0; q < 8; ++q) {
                    dfma(acc, c4[q].x, m4[q].x);
                    dfma(acc, c4[q].y, m4[q].y);
                }
                rv[tid] = ov[tid] - dsum(acc);
            }
        }
        __syncthreads();

        // ---- P2: S = CS@C^T + 0.03 I; write S out ----
        {
            int i = tid >> 4, j = tid & 15;
            const ulonglong2* a4 = (const ulonglong2*)&CSr[i][0];
            const ulonglong2* c4 = (const ulonglong2*)&Ct[j][0];
            u64 acc = 0;
            #pragma unroll
            for (int q = 0; q < 8; ++q) {
                dfma(acc, a4[q].x, c4[q].x);
                dfma(acc, a4[q].y, c4[q].y);
            }
            float s = ((i == j) ? 0.03f : 0.f) + dsum(acc);
            Ssh[i][j] = s;
            out_S[tb * 256 + tid] = s;
        }
        __syncthreads();

        // ---- P3: warp0 scalar GJ inverse; warps 1-7: U, V, Amu, Dch, R20,
        //          lm, lazy chain step ----
        if (wid == 0) {
            const int lrow = lane & 15;
            float M[16];
            const float4* sr = (const float4*)&Ssh[lrow][0];
            #pragma unroll
            for (int q = 0; q < 4; ++q) {
                float4 v = sr[q];
                M[4 * q + 0] = v.x; M[4 * q + 1] = v.y;
                M[4 * q + 2] = v.z; M[4 * q + 3] = v.w;
            }
            #pragma unroll
            for (int j = 0; j < 16; ++j) {
                float pj = __shfl_sync(0xffffffffu, M[j], j);
                float ip;
                asm("rcp.approx.ftz.f32 %0, %1;" : "=f"(ip) : "f"(pj));
                float f  = M[j];
                bool isj = (lrow == j);
                #pragma unroll
                for (int kk = 1; kk < 16; ++kk) {
                    int k = (j + kk) & 15;     // k = j+1 first: shortens pivot chain
                    float rj = __shfl_sync(0xffffffffu, M[k], j);
                    float v  = rj * ip;
                    M[k] = isj ? v : fmaf(-f, v, M[k]);
                }
                M[j] = isj ? ip : (-f * ip);
            }
            if (lane < 16) {
                float4* dst = (float4*)&Sinv[lane][0];
                #pragma unroll
                for (int q = 0; q < 4; ++q)
                    dst[q] = make_float4(M[4 * q], M[4 * q + 1], M[4 * q + 2], M[4 * q + 3]);
            }
        } else {
            int ww   = wid - 1;     // 0..6
            int wtid = tid - 32;    // 0..223
            if (wtid < 16) {
                float4 v = make_float4(0, 0, 0, 0);
                if (wtid >= 8) v = *(const float4*)&chain[t >> 2][(wtid - 8) * 4];
                *(float4*)(out_lm + tb * 64 + wtid * 4) = v;
            }
            // lazy chain: chain[j] = A2 @ chain[j-1] at t%4==1 (warp 6, 4-row warp)
            if (ww == 5 && (t & 3) == 1 && t <= 89) {
                int j = (t >> 2) + 1;
                const ulonglong2* a2 = (const ulonglong2*)&A2sh[lane][0];
                const ulonglong2* ch = (const ulonglong2*)&chain[j - 1][0];
                u64 acc = 0;
                #pragma unroll
                for (int q = 0; q < 8; ++q) {
                    dfma(acc, a2[q].x, ch[q].x);
                    dfma(acc, a2[q].y, ch[q].y);
                }
                chain[j][lane] = dsum(acc);
            }
            if (t + 1 < T_STEPS) {
                // U = A @ sigma (rows ww + 7m), V = A @ W
                ulonglong2 wr[8];
                #pragma unroll
                for (int q = 0; q < 8; ++q)
                    wr[q] = ((const ulonglong2*)&CSr[lane & 15][0])[q];
                #pragma unroll
                for (int m = 0; m < 5; ++m) {
                    int r = ww + 7 * m;
                    if (r < 32) {
                        const ulonglong2* ar = (const ulonglong2*)&Am[r][0];
                        u64 ua = 0, va = 0;
                        #pragma unroll
                        for (int q = 0; q < 8; ++q) {
                            ulonglong2 a = ar[q];
                            dfma(ua, a.x, scol[q].x);  dfma(ua, a.y, scol[q].y);
                            dfma(va, a.x, wr[q].x);    dfma(va, a.y, wr[q].y);
                        }
                        Ush[r][lane] = dsum(ua);
                        Vsh[r][lane & 15] = dsum(va);
                    }
                }
                if (ww == 6) {   // Amu + Dch (warp 7, lightest U load)
                    const ulonglong2* al7 = (const ulonglong2*)&Am[lane][0];
                    const ulonglong2* dl7 = (const ulonglong2*)&Dm[lane][0];
                    const ulonglong2* m4  = (const ulonglong2*)muc;
                    const ulonglong2* ch  = (const ulonglong2*)&chain[t >> 2][0];
                    u64 am = 0, dc = 0;
                    #pragma unroll
                    for (int q = 0; q < 8; ++q) {
                        dfma(am, al7[q].x, m4[q].x);  dfma(am, al7[q].y, m4[q].y);
                        dfma(dc, dl7[q].x, ch[q].x);  dfma(dc, dl7[q].y, ch[q].y);
                    }
                    amv[lane]  = dsum(am);
                    dchv[lane] = dsum(dc);
                }
                if (t < 4) {     // R20 = 20 * D @ D^T
                    ulonglong2 dcol[8];
                    #pragma unroll
                    for (int q = 0; q < 8; ++q)
                        dcol[q] = ((const ulonglong2*)&Dm[lane][0])[q];
                    #pragma unroll
                    for (int m = 0; m < 5; ++m) {
                        int r = ww + 7 * m;
                        if (r < 32) {
                            const ulonglong2* dr = (const ulonglong2*)&Dm[r][0];
                            u64 acc = 0;
                            #pragma unroll
                            for (int q = 0; q < 8; ++q) {
                                dfma(acc, dr[q].x, dcol[q].x);
                                dfma(acc, dr[q].y, dcol[q].y);
                            }
                            Rsh[r][lane] = 20.f * dsum(acc);
                        }
                    }
                }
            }
        }
        __syncthreads();

        // ---- P4: K = W@Sinv, G = V@Sinv (register-carry wl/vl to P5);
        //          al load; t1 rows 0,1; STS next C/obs ----
        ulonglong2 al[8];     // A row `lane` (used for t1)
        ulonglong2 wl[4];     // CSc[lane] — carried to P5 for sigf
        ulonglong2 vl[4];     // Vsh[lane] — carried to P5 for sigma'
        float t1a = 0.f, t1b = 0.f;   // (U A^T)[wid][lane], [wid+8][lane]
        {
            const ulonglong2* i0 = (const ulonglong2*)&Sinv[wid][0];
            const ulonglong2* i1 = (const ulonglong2*)&Sinv[wid + 8][0];
            {
                #pragma unroll
                for (int q = 0; q < 4; ++q) wl[q] = ((const ulonglong2*)&CSc[lane][0])[q];
                u64 a0 = 0, a1 = 0;
                #pragma unroll
                for (int q = 0; q < 4; ++q) {
                    ulonglong2 x = wl[q];
                    dfma(a0, x.x, i0[q].x);  dfma(a0, x.y, i0[q].y);
                    dfma(a1, x.x, i1[q].x);  dfma(a1, x.y, i1[q].y);
                }
                Ksh[lane][wid]     = dsum(a0);
                Ksh[lane][wid + 8] = dsum(a1);
            }
            if (t + 1 < T_STEPS) {
                #pragma unroll
                for (int q = 0; q < 4; ++q) vl[q] = ((const ulonglong2*)&Vsh[lane][0])[q];
                u64 g0 = 0, g1 = 0;
                #pragma unroll
                for (int q = 0; q < 4; ++q) {
                    ulonglong2 x = vl[q];
                    dfma(g0, x.x, i0[q].x);  dfma(g0, x.y, i0[q].y);
                    dfma(g1, x.x, i1[q].x);  dfma(g1, x.y, i1[q].y);
                }
                Gsh[lane][wid]     = dsum(g0);
                Gsh[lane][wid + 8] = dsum(g1);
                #pragma unroll
                for (int q = 0; q < 8; ++q) al[q] = ((const ulonglong2*)&Am[lane][0])[q];
                // t1 rows 0,1 (Ush stable since P3)
                const ulonglong2* u0 = (const ulonglong2*)&Ush[wid][0];
                const ulonglong2* u1 = (const ulonglong2*)&Ush[wid + 8][0];
                u64 ta = 0, tb4 = 0;
                #pragma unroll
                for (int q = 0; q < 8; ++q) {
                    dfma(ta,  u0[q].x, al[q].x);  dfma(ta,  u0[q].y, al[q].y);
                    dfma(tb4, u1[q].x, al[q].x);  dfma(tb4, u1[q].y, al[q].y);
                }
                t1a = dsum(ta);  t1b = dsum(tb4);
                if (tid < 128) *(float4*)&Ct[tid >> 3][(tid & 7) * 4] = rC;
                if (tid < 16)  ov[tid] = rO;
            }
        }
        __syncthreads();

        // ---- P5: sigz -> sigf; sigma' = t1 - G V^T + Q (+R20); mu' ----
        {
            #pragma unroll
            for (int ii = 0; ii < 4; ++ii) {
                int i = wid + 8 * ii;
                const ulonglong2* kr = (const ulonglong2*)&Ksh[i][0];
                u64 acc = 0;
                #pragma unroll
                for (int q = 0; q < 4; ++q) {
                    dfma(acc, kr[q].x, wl[q].x);
                    dfma(acc, kr[q].y, wl[q].y);
                }
                out_sigf[tb * 1024 + i * 32 + lane] = sig_il[ii] - dsum(acc);
            }
            if (tid < 32) {   // mu_filt
                const ulonglong2* kk = (const ulonglong2*)&Ksh[tid][0];
                const ulonglong2* r4 = (const ulonglong2*)rv;
                u64 acc = 0;
                #pragma unroll
                for (int q = 0; q < 4; ++q) {
                    dfma(acc, kk[q].x, r4[q].x);
                    dfma(acc, kk[q].y, r4[q].y);
                }
                out_muf[tb * 32 + tid] = muc[tid] + dsum(acc);
            }
            if (t + 1 < T_STEPS) {
                const size_t tb2 = tb + BATCH;   // (t+1)*BATCH + b
                // t1 rows 2,3 computed here; rows 0,1 carried from P4
                float t1c, t1d;
                {
                    const ulonglong2* u2 = (const ulonglong2*)&Ush[wid + 16][0];
                    const ulonglong2* u3 = (const ulonglong2*)&Ush[wid + 24][0];
                    u64 tc = 0, td = 0;
                    #pragma unroll
                    for (int q = 0; q < 8; ++q) {
                        dfma(tc, u2[q].x, al[q].x);  dfma(tc, u2[q].y, al[q].y);
                        dfma(td, u3[q].x, al[q].x);  dfma(td, u3[q].y, al[q].y);
                    }
                    t1c = dsum(tc);  t1d = dsum(td);
                }
                float t1v[4] = {t1a, t1b, t1c, t1d};
                #pragma unroll
                for (int ii = 0; ii < 4; ++ii) {
                    int i = wid + 8 * ii;
                    const ulonglong2* gr = (const ulonglong2*)&Gsh[i][0];
                    u64 acc = 0;
                    #pragma unroll
                    for (int q = 0; q < 4; ++q) {
                        dfma(acc, gr[q].x, vl[q].x);
                        dfma(acc, gr[q].y, vl[q].y);
                    }
                    float s = t1v[ii] - dsum(acc);
                    if (i == lane) s += 0.08f;
                    if (t < 4)     s += Rsh[i][lane];
                    sgn[i][lane] = s;
                    out_sigp[tb2 * 1024 + i * 32 + lane] = s;
                }
                if (tid >= 32 && tid < 64) {   // mu' = Amu + G r + Dch
                    int l = lane;
                    const ulonglong2* gr = (const ulonglong2*)&Gsh[l][0];
                    const ulonglong2* r4 = (const ulonglong2*)rv;
                    u64 acc = 0;
                    #pragma unroll
                    for (int q = 0; q < 4; ++q) {
                        dfma(acc, gr[q].x, r4[q].x);
                        dfma(acc, gr[q].y, r4[q].y);
                    }
                    float m = amv[l] + dchv[l] + dsum(acc);
                    mun[l] = m;
                    out_mup[tb2 * 32 + l] = m;
                }
            }
        }
        __syncthreads();
    }
}

extern "C" void kernel_launch(void* const* d_in, const int* in_sizes, int n_in,
                              void* d_out, int out_size) {
    const float* obs = (const float*)d_in[0];
    const float* A   = (const float*)d_in[1];
    const float* C   = (const float*)d_in[2];
    const float* D   = (const float*)d_in[3];
    kalman_kernel<<<BATCH + 20, 256>>>(obs, A, C, D, (float*)d_out);
}

// round 16
// speedup vs baseline: 1.3737x; 1.0311x over previous
#include <cuda_runtime.h>

#define T_STEPS 96
#define BATCH   128

// Output section offsets (floats), tuple order:
// mu_filt, sigma_filt, mu_pred, sigma_pred, latent_means, latent_variances, S
#define OFF_MUF   0
#define OFF_SIGF  393216
#define OFF_MUP   12976128
#define OFF_SIGP  13369344
#define OFF_LM    25952256
#define OFF_LV    26738688
#define OFF_S     51904512

#define PZ 36   // 32-wide rows padded: 144B, 16B-aligned
#define PA 20   // 16-wide rows padded: 80B, 16B-aligned

typedef unsigned long long u64;

// packed f32x2 fused multiply-add: acc.{lo,hi} += a.{lo,hi} * b.{lo,hi}
__device__ __forceinline__ void dfma(u64& acc, u64 a, u64 b) {
    asm("fma.rn.f32x2 %0, %1, %2, %0;" : "+l"(acc) : "l"(a), "l"(b));
}
__device__ __forceinline__ float dsum(u64 a) {
    unsigned lo, hi;
    asm("mov.b64 {%0, %1}, %2;" : "=r"(lo), "=r"(hi) : "l"(a));
    return __uint_as_float(lo) + __uint_as_float(hi);
}

__global__ __launch_bounds__(256, 1)
void kalman_kernel(const float* __restrict__ obs,
                   const float* __restrict__ Ag_all,
                   const float* __restrict__ Cg_all,
                   const float* __restrict__ Dg_all,
                   float* __restrict__ out)
{
    const int tid  = threadIdx.x;

    // ---------------- writer blocks: latent_variances (input-independent) ----
    if (blockIdx.x >= BATCH) {
        float* out_lv = out + OFF_LV;
        int wb = blockIdx.x - BATCH;          // 0..19
        for (int t = 0; t < T_STEPS; ++t) {
            float d0 = (t >= 2) ? 0.08f : 0.f;
            float d1 = (t <  4) ? 20.f  : 0.f;
            float4* dst = (float4*)(out_lv + (size_t)t * BATCH * 2048);
            for (int e4 = wb * 256 + tid; e4 < 65536; e4 += 20 * 256) {
                int v2 = (e4 * 4) & 2047;
                int l  = v2 >> 10;
                int ij = v2 & 1023;
                int i  = ij >> 5, j0 = ij & 31;
                float dv = l ? d1 : d0;
                bool hit = ((i >> 2) == (j0 >> 2));
                float4 v;
                v.x = (hit && (i & 3) == 0) ? dv : 0.f;
                v.y = (hit && (i & 3) == 1) ? dv : 0.f;
                v.z = (hit && (i & 3) == 2) ? dv : 0.f;
                v.w = (hit && (i & 3) == 3) ? dv : 0.f;
                dst[e4] = v;
            }
        }
        return;
    }

    const int b    = blockIdx.x;
    const int lane = tid & 31;
    const int wid  = tid >> 5;       // 0..7

    __shared__ __align__(16) float sigB[2][32][PZ]; // sigma ping-pong (symmetric)
    __shared__ __align__(16) float Ush [32][PZ];    // U = A @ sigma
    __shared__ __align__(16) float Rsh [32][PZ];    // 20*D@D^T (t<4)
    __shared__ __align__(16) float Am  [32][PZ];    // A[b,t+1,0]
    __shared__ __align__(16) float Dm  [32][PZ];    // D[b,t+1,0]
    __shared__ __align__(16) float Ct  [16][PZ];    // C[b,t]
    __shared__ __align__(16) float CSr [16][PZ];    // CS = C@sigma, row-major
    __shared__ __align__(16) float CSc [32][PA];    // W = sigma C^T (rows = z)
    __shared__ __align__(16) float Vsh [32][PA];    // V = A @ W
    __shared__ __align__(16) float Gsh [32][PA];    // G = V @ Sinv
    __shared__ __align__(16) float Ksh [32][PA];    // K = W @ Sinv
    __shared__ __align__(16) float Sinv[16][PA];
    __shared__ __align__(16) float Ssh [16][PA];
    __shared__ __align__(16) float muB[2][32];
    __shared__ __align__(16) float amv[32], dchv[32], rv[16], ov[16];
    __shared__ __align__(16) float chain[24][32];

    float* out_muf  = out + OFF_MUF;
    float* out_sigf = out + OFF_SIGF;
    float* out_mup  = out + OFF_MUP;
    float* out_sigp = out + OFF_SIGP;
    float* out_lm   = out + OFF_LM;
    float* out_S    = out + OFF_S;

    // ---------------- Prologue: top-level latent chain ----------------
    if (tid < 32) chain[0][tid] = 0.01f;
    {
        float4 pf[3];
        #pragma unroll
        for (int s = 0; s < 3; ++s) {
            const float* Ag = Ag_all + ((size_t)(b * T_STEPS + 4 * (s + 1)) * 3 + 2) * 1024;
            pf[s] = *(const float4*)(Ag + tid * 4);
        }
        __syncthreads();
        for (int j = 1; j <= 23; ++j) {
            int s = (j - 1) % 3;
            *(float4*)&Am[tid >> 3][(tid & 7) * 4] = pf[s];
            if (j + 3 <= 23) {
                const float* Ag = Ag_all + ((size_t)(b * T_STEPS + 4 * (j + 3)) * 3 + 2) * 1024;
                pf[s] = *(const float4*)(Ag + tid * 4);
            }
            __syncthreads();
            if (tid < 32) {
                const ulonglong2* ar = (const ulonglong2*)&Am[tid][0];
                const ulonglong2* ch = (const ulonglong2*)&chain[j - 1][0];
                u64 acc = 0;
                #pragma unroll
                for (int q = 0; q < 8; ++q) {
                    dfma(acc, ar[q].x, ch[q].x);
                    dfma(acc, ar[q].y, ch[q].y);
                }
                chain[j][tid] = dsum(acc);
            }
            __syncthreads();
        }
    }

    // ---------------- init state + t=0 prior outputs + step-0/1 operands ----
    float4 rA, rD, rC = make_float4(0, 0, 0, 0);
    float  rO = 0.f;
    {
        if (tid < 128)
            *(float4*)&Ct[tid >> 3][(tid & 7) * 4] =
                *(const float4*)(Cg_all + (size_t)(b * T_STEPS) * 512 + tid * 4);
        if (tid < 16) ov[tid] = obs[(size_t)b * 16 + tid];
        {
            int row = tid >> 3, c0 = (tid & 7) * 4;
            float4 sv = make_float4(0, 0, 0, 0);
            if (row >= c0 && row < c0 + 4) {
                int d = row - c0;
                sv.x = (d == 0) ? 20.f : 0.f;
                sv.y = (d == 1) ? 20.f : 0.f;
                sv.z = (d == 2) ? 20.f : 0.f;
                sv.w = (d == 3) ? 20.f : 0.f;
            }
            *(float4*)&sigB[0][row][c0] = sv;
            *(float4*)(out_sigp + (size_t)b * 1024 + tid * 4) = sv;
        }
        if (tid < 32) muB[0][tid] = 0.f;
        if (tid < 8)
            *(float4*)(out_mup + (size_t)b * 32 + tid * 4) = make_float4(0, 0, 0, 0);
        rA = *(const float4*)(Ag_all + (size_t)(b * T_STEPS + 1) * 3 * 1024 + tid * 4);
        rD = *(const float4*)(Dg_all + (size_t)(b * T_STEPS + 1) * 2 * 1024 + tid * 4);
    }
    __syncthreads();

    // ---------------- main sequential filter ----------------
    for (int t = 0; t < T_STEPS; ++t) {
        const size_t tb = (size_t)t * BATCH + b;
        float (*sgc)[PZ] = sigB[t & 1];
        float (*sgn)[PZ] = sigB[(t + 1) & 1];
        float* muc = muB[t & 1];
        float* mun = muB[(t + 1) & 1];

        ulonglong2 scol[8];   // register-cached sigma column `lane` (reused in P3)
        float sig_il[4];      // sgc[wid+8ii][lane] via symmetry (used in P5)

        // ---- P1: STS A/D[t+1]; prefetch; CS = C@sigma; r = o - C@mu ----
        {
            int ar2 = tid >> 3, ac = (tid & 7) * 4;
            *(float4*)&Am[ar2][ac] = rA;
            *(float4*)&Dm[ar2][ac] = rD;
            if (t + 2 < T_STEPS) {
                rA = *(const float4*)(Ag_all + (size_t)(b * T_STEPS + t + 2) * 3 * 1024 + tid * 4);
                rD = *(const float4*)(Dg_all + (size_t)(b * T_STEPS + t + 2) * 2 * 1024 + tid * 4);
            }
            if (t + 1 < T_STEPS) {
                if (tid < 128)
                    rC = *(const float4*)(Cg_all + (size_t)(b * T_STEPS + t + 1) * 512 + tid * 4);
                if (tid < 16)
                    rO = obs[(size_t)((t + 1) * BATCH + b) * 16 + tid];
            }
            const ulonglong2* sc = (const ulonglong2*)&sgc[lane][0];
            const ulonglong2* c0 = (const ulonglong2*)&Ct[wid][0];
            const ulonglong2* c1 = (const ulonglong2*)&Ct[wid + 8][0];
            u64 a0 = 0, a1 = 0;
            #pragma unroll
            for (int q = 0; q < 8; ++q) {
                ulonglong2 g = sc[q];
                scol[q] = g;
                ulonglong2 x0 = c0[q], x1 = c1[q];
                dfma(a0, x0.x, g.x);  dfma(a0, x0.y, g.y);
                dfma(a1, x1.x, g.x);  dfma(a1, x1.y, g.y);
            }
            float s0 = dsum(a0), s1 = dsum(a1);
            CSr[wid][lane] = s0;      CSr[wid + 8][lane] = s1;
            CSc[lane][wid] = s0;      CSc[lane][wid + 8] = s1;
            // sig_il[ii] = sgc[wid+8ii][lane] == sgc[lane][wid+8ii] (symmetry):
            // element (wid+8ii) of the register-cached column. Warp-uniform selects.
            #pragma unroll
            for (int ii = 0; ii < 4; ++ii) {
                ulonglong2 sq = scol[2 * ii + (wid >> 2)];
                u64 part = (wid & 2) ? sq.y : sq.x;
                unsigned lo, hi;
                asm("mov.b64 {%0, %1}, %2;" : "=r"(lo), "=r"(hi) : "l"(part));
                sig_il[ii] = __uint_as_float((wid & 1) ? hi : lo);
            }
            if (tid < 16) {
                const ulonglong2* c4 = (const ulonglong2*)&Ct[tid][0];
                const ulonglong2* m4 = (const ulonglong2*)muc;
                u64 acc = 0;
                #pragma unroll
                for (int q = 0; q < 8; ++q) {
                    dfma(acc, c4[q].x, m4[q].x);
                    dfma(acc, c4[q].y, m4[q].y);
                }
                rv[tid] = ov[tid] - dsum(acc);
            }
        }
        __syncthreads();

        // ---- P2: S = CS@C^T + 0.03 I; write S out ----
        {
            int i = tid >> 4, j = tid & 15;
            const ulonglong2* a4 = (const ulonglong2*)&CSr[i][0];
            const ulonglong2* c4 = (const ulonglong2*)&Ct[j][0];
            u64 acc = 0;
            #pragma unroll
            for (int q = 0; q < 8; ++q) {
                dfma(acc, a4[q].x, c4[q].x);
                dfma(acc, a4[q].y, c4[q].y);
            }
            float s = ((i == j) ? 0.03f : 0.f) + dsum(acc);
            Ssh[i][j] = s;
            out_S[tb * 256 + tid] = s;
        }
        __syncthreads();

        // ---- P3: warp0 scalar GJ inverse; warps 1-7: U, V, Amu, Dch, R20 ----
        if (wid == 0) {
            const int lrow = lane & 15;
            float M[16];
            const float4* sr = (const float4*)&Ssh[lrow][0];
            #pragma unroll
            for (int q = 0; q < 4; ++q) {
                float4 v = sr[q];
                M[4 * q + 0] = v.x; M[4 * q + 1] = v.y;
                M[4 * q + 2] = v.z; M[4 * q + 3] = v.w;
            }
            #pragma unroll
            for (int j = 0; j < 16; ++j) {
                float pj = __shfl_sync(0xffffffffu, M[j], j);
                float ip;
                asm("rcp.approx.ftz.f32 %0, %1;" : "=f"(ip) : "f"(pj));
                float f  = M[j];
                bool isj = (lrow == j);
                #pragma unroll
                for (int kk = 1; kk < 16; ++kk) {
                    int k = (j + kk) & 15;     // k = j+1 first: shortens pivot chain
                    float rj = __shfl_sync(0xffffffffu, M[k], j);
                    float v  = rj * ip;
                    M[k] = isj ? v : fmaf(-f, v, M[k]);
                }
                M[j] = isj ? ip : (-f * ip);
            }
            if (lane < 16) {
                float4* dst = (float4*)&Sinv[lane][0];
                #pragma unroll
                for (int q = 0; q < 4; ++q)
                    dst[q] = make_float4(M[4 * q], M[4 * q + 1], M[4 * q + 2], M[4 * q + 3]);
            }
        } else {
            int ww   = wid - 1;     // 0..6
            int wtid = tid - 32;    // 0..223
            if (wtid < 16) {
                float4 v = make_float4(0, 0, 0, 0);
                if (wtid >= 8) v = *(const float4*)&chain[t >> 2][(wtid - 8) * 4];
                *(float4*)(out_lm + tb * 64 + wtid * 4) = v;
            }
            if (t + 1 < T_STEPS) {
                // U = A @ sigma (rows ww + 7m), V = A @ W
                ulonglong2 wr[8];
                #pragma unroll
                for (int q = 0; q < 8; ++q)
                    wr[q] = ((const ulonglong2*)&CSr[lane & 15][0])[q];
                #pragma unroll
                for (int m = 0; m < 5; ++m) {
                    int r = ww + 7 * m;
                    if (r < 32) {
                        const ulonglong2* ar = (const ulonglong2*)&Am[r][0];
                        u64 ua = 0, va = 0;
                        #pragma unroll
                        for (int q = 0; q < 8; ++q) {
                            ulonglong2 a = ar[q];
                            dfma(ua, a.x, scol[q].x);  dfma(ua, a.y, scol[q].y);
                            dfma(va, a.x, wr[q].x);    dfma(va, a.y, wr[q].y);
                        }
                        Ush[r][lane] = dsum(ua);
                        Vsh[r][lane & 15] = dsum(va);
                    }
                }
                if (ww == 6) {   // Amu + Dch (warp 7, lightest U load)
                    const ulonglong2* al7 = (const ulonglong2*)&Am[lane][0];
                    const ulonglong2* dl7 = (const ulonglong2*)&Dm[lane][0];
                    const ulonglong2* m4  = (const ulonglong2*)muc;
                    const ulonglong2* ch  = (const ulonglong2*)&chain[t >> 2][0];
                    u64 am = 0, dc = 0;
                    #pragma unroll
                    for (int q = 0; q < 8; ++q) {
                        dfma(am, al7[q].x, m4[q].x);  dfma(am, al7[q].y, m4[q].y);
                        dfma(dc, dl7[q].x, ch[q].x);  dfma(dc, dl7[q].y, ch[q].y);
                    }
                    amv[lane]  = dsum(am);
                    dchv[lane] = dsum(dc);
                }
                if (t < 4) {     // R20 = 20 * D @ D^T
                    ulonglong2 dcol[8];
                    #pragma unroll
                    for (int q = 0; q < 8; ++q)
                        dcol[q] = ((const ulonglong2*)&Dm[lane][0])[q];
                    #pragma unroll
                    for (int m = 0; m < 5; ++m) {
                        int r = ww + 7 * m;
                        if (r < 32) {
                            const ulonglong2* dr = (const ulonglong2*)&Dm[r][0];
                            u64 acc = 0;
                            #pragma unroll
                            for (int q = 0; q < 8; ++q) {
                                dfma(acc, dr[q].x, dcol[q].x);
                                dfma(acc, dr[q].y, dcol[q].y);
                            }
                            Rsh[r][lane] = 20.f * dsum(acc);
                        }
                    }
                }
            }
        }
        __syncthreads();

        // ---- P4: K = W@Sinv, G = V@Sinv (register-carry wl/vl to P5);
        //          al load; t1 rows 0,1; STS next C/obs ----
        ulonglong2 al[8];     // A row `lane` (used for t1)
        ulonglong2 wl[4];     // CSc[lane] — carried to P5 for sigf
        ulonglong2 vl[4];     // Vsh[lane] — carried to P5 for sigma'
        float t1a = 0.f, t1b = 0.f;   // (U A^T)[wid][lane], [wid+8][lane]
        {
            const ulonglong2* i0 = (const ulonglong2*)&Sinv[wid][0];
            const ulonglong2* i1 = (const ulonglong2*)&Sinv[wid + 8][0];
            {
                #pragma unroll
                for (int q = 0; q < 4; ++q) wl[q] = ((const ulonglong2*)&CSc[lane][0])[q];
                u64 a0 = 0, a1 = 0;
                #pragma unroll
                for (int q = 0; q < 4; ++q) {
                    ulonglong2 x = wl[q];
                    dfma(a0, x.x, i0[q].x);  dfma(a0, x.y, i0[q].y);
                    dfma(a1, x.x, i1[q].x);  dfma(a1, x.y, i1[q].y);
                }
                Ksh[lane][wid]     = dsum(a0);
                Ksh[lane][wid + 8] = dsum(a1);
            }
            if (t + 1 < T_STEPS) {
                #pragma unroll
                for (int q = 0; q < 4; ++q) vl[q] = ((const ulonglong2*)&Vsh[lane][0])[q];
                u64 g0 = 0, g1 = 0;
                #pragma unroll
                for (int q = 0; q < 4; ++q) {
                    ulonglong2 x = vl[q];
                    dfma(g0, x.x, i0[q].x);  dfma(g0, x.y, i0[q].y);
                    dfma(g1, x.x, i1[q].x);  dfma(g1, x.y, i1[q].y);
                }
                Gsh[lane][wid]     = dsum(g0);
                Gsh[lane][wid + 8] = dsum(g1);
                #pragma unroll
                for (int q = 0; q < 8; ++q) al[q] = ((const ulonglong2*)&Am[lane][0])[q];
                // t1 rows 0,1 (Ush stable since P3)
                const ulonglong2* u0 = (const ulonglong2*)&Ush[wid][0];
                const ulonglong2* u1 = (const ulonglong2*)&Ush[wid + 8][0];
                u64 ta = 0, tb4 = 0;
                #pragma unroll
                for (int q = 0; q < 8; ++q) {
                    dfma(ta,  u0[q].x, al[q].x);  dfma(ta,  u0[q].y, al[q].y);
                    dfma(tb4, u1[q].x, al[q].x);  dfma(tb4, u1[q].y, al[q].y);
                }
                t1a = dsum(ta);  t1b = dsum(tb4);
                if (tid < 128) *(float4*)&Ct[tid >> 3][(tid & 7) * 4] = rC;
                if (tid < 16)  ov[tid] = rO;
            }
        }
        __syncthreads();

        // ---- P5: sigz -> sigf; sigma' = t1 - G V^T + Q (+R20); mu' ----
        {
            #pragma unroll
            for (int ii = 0; ii < 4; ++ii) {
                int i = wid + 8 * ii;
                const ulonglong2* kr = (const ulonglong2*)&Ksh[i][0];
                u64 acc = 0;
                #pragma unroll
                for (int q = 0; q < 4; ++q) {
                    dfma(acc, kr[q].x, wl[q].x);
                    dfma(acc, kr[q].y, wl[q].y);
                }
                out_sigf[tb * 1024 + i * 32 + lane] = sig_il[ii] - dsum(acc);
            }
            if (tid < 32) {   // mu_filt
                const ulonglong2* kk = (const ulonglong2*)&Ksh[tid][0];
                const ulonglong2* r4 = (const ulonglong2*)rv;
                u64 acc = 0;
                #pragma unroll
                for (int q = 0; q < 4; ++q) {
                    dfma(acc, kk[q].x, r4[q].x);
                    dfma(acc, kk[q].y, r4[q].y);
                }
                out_muf[tb * 32 + tid] = muc[tid] + dsum(acc);
            }
            if (t + 1 < T_STEPS) {
                const size_t tb2 = tb + BATCH;   // (t+1)*BATCH + b
                // t1 rows 2,3 computed here; rows 0,1 carried from P4
                float t1c, t1d;
                {
                    const ulonglong2* u2 = (const ulonglong2*)&Ush[wid + 16][0];
                    const ulonglong2* u3 = (const ulonglong2*)&Ush[wid + 24][0];
                    u64 tc = 0, td = 0;
                    #pragma unroll
                    for (int q = 0; q < 8; ++q) {
                        dfma(tc, u2[q].x, al[q].x);  dfma(tc, u2[q].y, al[q].y);
                        dfma(td, u3[q].x, al[q].x);  dfma(td, u3[q].y, al[q].y);
                    }
                    t1c = dsum(tc);  t1d = dsum(td);
                }
                float t1v[4] = {t1a, t1b, t1c, t1d};
                #pragma unroll
                for (int ii = 0; ii < 4; ++ii) {
                    int i = wid + 8 * ii;
                    const ulonglong2* gr = (const ulonglong2*)&Gsh[i][0];
                    u64 acc = 0;
                    #pragma unroll
                    for (int q = 0; q < 4; ++q) {
                        dfma(acc, gr[q].x, vl[q].x);
                        dfma(acc, gr[q].y, vl[q].y);
                    }
                    float s = t1v[ii] - dsum(acc);
                    if (i == lane) s += 0.08f;
                    if (t < 4)     s += Rsh[i][lane];
                    sgn[i][lane] = s;
                    out_sigp[tb2 * 1024 + i * 32 + lane] = s;
                }
                if (tid >= 32 && tid < 64) {   // mu' = Amu + G r + Dch
                    int l = lane;
                    const ulonglong2* gr = (const ulonglong2*)&Gsh[l][0];
                    const ulonglong2* r4 = (const ulonglong2*)rv;
                    u64 acc = 0;
                    #pragma unroll
                    for (int q = 0; q < 4; ++q) {
                        dfma(acc, gr[q].x, r4[q].x);
                        dfma(acc, gr[q].y, r4[q].y);
                    }
                    float m = amv[l] + dchv[l] + dsum(acc);
                    mun[l] = m;
                    out_mup[tb2 * 32 + l] = m;
                }
            }
        }
        __syncthreads();
    }
}

extern "C" void kernel_launch(void* const* d_in, const int* in_sizes, int n_in,
                              void* d_out, int out_size) {
    const float* obs = (const float*)d_in[0];
    const float* A   = (const float*)d_in[1];
    const float* C   = (const float*)d_in[2];
    const float* D   = (const float*)d_in[3];
    kalman_kernel<<<BATCH + 20, 256>>>(obs, A, C, D, (float*)d_out);
}

// round 17
// speedup vs baseline: 1.5469x; 1.1260x over previous
#include <cuda_runtime.h>

#define T_STEPS 96
#define BATCH   128

// Output section offsets (floats), tuple order:
// mu_filt, sigma_filt, mu_pred, sigma_pred, latent_means, latent_variances, S
#define OFF_MUF   0
#define OFF_SIGF  393216
#define OFF_MUP   12976128
#define OFF_SIGP  13369344
#define OFF_LM    25952256
#define OFF_LV    26738688
#define OFF_S     51904512

#define PZ 36   // 32-wide rows padded: 144B, 16B-aligned
#define PA 20   // 16-wide rows padded: 80B, 16B-aligned

typedef unsigned long long u64;

// packed f32x2 fused multiply-add: acc.{lo,hi} += a.{lo,hi} * b.{lo,hi}
__device__ __forceinline__ void dfma(u64& acc, u64 a, u64 b) {
    asm("fma.rn.f32x2 %0, %1, %2, %0;" : "+l"(acc) : "l"(a), "l"(b));
}
__device__ __forceinline__ float dsum(u64 a) {
    unsigned lo, hi;
    asm("mov.b64 {%0, %1}, %2;" : "=r"(lo), "=r"(hi) : "l"(a));
    return __uint_as_float(lo) + __uint_as_float(hi);
}

__global__ __launch_bounds__(256, 1)
void kalman_kernel(const float* __restrict__ obs,
                   const float* __restrict__ Ag_all,
                   const float* __restrict__ Cg_all,
                   const float* __restrict__ Dg_all,
                   float* __restrict__ out)
{
    const int tid  = threadIdx.x;

    // ---------------- writer blocks: latent_variances (input-independent) ----
    if (blockIdx.x >= BATCH) {
        float* out_lv = out + OFF_LV;
        int wb = blockIdx.x - BATCH;          // 0..19
        for (int t = 0; t < T_STEPS; ++t) {
            float d0 = (t >= 2) ? 0.08f : 0.f;
            float d1 = (t <  4) ? 20.f  : 0.f;
            float4* dst = (float4*)(out_lv + (size_t)t * BATCH * 2048);
            for (int e4 = wb * 256 + tid; e4 < 65536; e4 += 20 * 256) {
                int v2 = (e4 * 4) & 2047;
                int l  = v2 >> 10;
                int ij = v2 & 1023;
                int i  = ij >> 5, j0 = ij & 31;
                float dv = l ? d1 : d0;
                bool hit = ((i >> 2) == (j0 >> 2));
                float4 v;
                v.x = (hit && (i & 3) == 0) ? dv : 0.f;
                v.y = (hit && (i & 3) == 1) ? dv : 0.f;
                v.z = (hit && (i & 3) == 2) ? dv : 0.f;
                v.w = (hit && (i & 3) == 3) ? dv : 0.f;
                dst[e4] = v;
            }
        }
        return;
    }

    const int b    = blockIdx.x;
    const int lane = tid & 31;
    const int wid  = tid >> 5;       // 0..7

    __shared__ __align__(16) float sigB[2][32][PZ]; // sigma ping-pong (symmetric)
    __shared__ __align__(16) float Ush [32][PZ];    // U = A @ sigma
    __shared__ __align__(16) float Rsh [32][PZ];    // 20*D@D^T (t<4)
    __shared__ __align__(16) float Am  [32][PZ];    // A[b,t+1,0]
    __shared__ __align__(16) float Dm  [32][PZ];    // D[b,t+1,0]
    __shared__ __align__(16) float Ct  [16][PZ];    // C[b,t]
    __shared__ __align__(16) float CSr [16][PZ];    // CS = C@sigma, row-major
    __shared__ __align__(16) float CSc [32][PA];    // W = sigma C^T (rows = z)
    __shared__ __align__(16) float Vsh [32][PA];    // V = A @ W
    __shared__ __align__(16) float Gsh [32][PA];    // G = V @ Sinv
    __shared__ __align__(16) float Ksh [32][PA];    // K = W @ Sinv
    __shared__ __align__(16) float Sinv[16][PA];
    __shared__ __align__(16) float Ssh [16][PA];
    __shared__ __align__(16) float muB[2][32];
    __shared__ __align__(16) float amv[32], dchv[32], rv[16], ov[16];
    __shared__ __align__(16) float chain[24][32];

    float* out_muf  = out + OFF_MUF;
    float* out_sigf = out + OFF_SIGF;
    float* out_mup  = out + OFF_MUP;
    float* out_sigp = out + OFF_SIGP;
    float* out_lm   = out + OFF_LM;
    float* out_S    = out + OFF_S;

    // ---------------- Prologue: top-level latent chain ----------------
    if (tid < 32) chain[0][tid] = 0.01f;
    {
        float4 pf[3];
        #pragma unroll
        for (int s = 0; s < 3; ++s) {
            const float* Ag = Ag_all + ((size_t)(b * T_STEPS + 4 * (s + 1)) * 3 + 2) * 1024;
            pf[s] = *(const float4*)(Ag + tid * 4);
        }
        __syncthreads();
        for (int j = 1; j <= 23; ++j) {
            int s = (j - 1) % 3;
            *(float4*)&Am[tid >> 3][(tid & 7) * 4] = pf[s];
            if (j + 3 <= 23) {
                const float* Ag = Ag_all + ((size_t)(b * T_STEPS + 4 * (j + 3)) * 3 + 2) * 1024;
                pf[s] = *(const float4*)(Ag + tid * 4);
            }
            __syncthreads();
            if (tid < 32) {
                const ulonglong2* ar = (const ulonglong2*)&Am[tid][0];
                const ulonglong2* ch = (const ulonglong2*)&chain[j - 1][0];
                u64 acc = 0;
                #pragma unroll
                for (int q = 0; q < 8; ++q) {
                    dfma(acc, ar[q].x, ch[q].x);
                    dfma(acc, ar[q].y, ch[q].y);
                }
                chain[j][tid] = dsum(acc);
            }
            __syncthreads();
        }
    }

    // ---------------- init state + t=0 prior outputs + step-0/1 operands ----
    float4 rA, rD, rC = make_float4(0, 0, 0, 0);
    float  rO = 0.f;
    {
        if (tid < 128)
            *(float4*)&Ct[tid >> 3][(tid & 7) * 4] =
                *(const float4*)(Cg_all + (size_t)(b * T_STEPS) * 512 + tid * 4);
        if (tid < 16) ov[tid] = obs[(size_t)b * 16 + tid];
        {
            int row = tid >> 3, c0 = (tid & 7) * 4;
            float4 sv = make_float4(0, 0, 0, 0);
            if (row >= c0 && row < c0 + 4) {
                int d = row - c0;
                sv.x = (d == 0) ? 20.f : 0.f;
                sv.y = (d == 1) ? 20.f : 0.f;
                sv.z = (d == 2) ? 20.f : 0.f;
                sv.w = (d == 3) ? 20.f : 0.f;
            }
            *(float4*)&sigB[0][row][c0] = sv;
            *(float4*)(out_sigp + (size_t)b * 1024 + tid * 4) = sv;
        }
        if (tid < 32) muB[0][tid] = 0.f;
        if (tid < 8)
            *(float4*)(out_mup + (size_t)b * 32 + tid * 4) = make_float4(0, 0, 0, 0);
        rA = *(const float4*)(Ag_all + (size_t)(b * T_STEPS + 1) * 3 * 1024 + tid * 4);
        rD = *(const float4*)(Dg_all + (size_t)(b * T_STEPS + 1) * 2 * 1024 + tid * 4);
    }
    __syncthreads();

    // ---------------- main sequential filter ----------------
    for (int t = 0; t < T_STEPS; ++t) {
        const size_t tb = (size_t)t * BATCH + b;
        float (*sgc)[PZ] = sigB[t & 1];
        float (*sgn)[PZ] = sigB[(t + 1) & 1];
        float* muc = muB[t & 1];
        float* mun = muB[(t + 1) & 1];

        ulonglong2 scol[8];   // register-cached sigma column `lane` (reused in P3)

        // ---- P1: STS A/D[t+1]; prefetch; CS = C@sigma; r = o - C@mu ----
        {
            int ar2 = tid >> 3, ac = (tid & 7) * 4;
            *(float4*)&Am[ar2][ac] = rA;
            *(float4*)&Dm[ar2][ac] = rD;
            if (t + 2 < T_STEPS) {
                rA = *(const float4*)(Ag_all + (size_t)(b * T_STEPS + t + 2) * 3 * 1024 + tid * 4);
                rD = *(const float4*)(Dg_all + (size_t)(b * T_STEPS + t + 2) * 2 * 1024 + tid * 4);
            }
            if (t + 1 < T_STEPS) {
                if (tid < 128)
                    rC = *(const float4*)(Cg_all + (size_t)(b * T_STEPS + t + 1) * 512 + tid * 4);
                if (tid < 16)
                    rO = obs[(size_t)((t + 1) * BATCH + b) * 16 + tid];
            }
            const ulonglong2* sc = (const ulonglong2*)&sgc[lane][0];
            const ulonglong2* c0 = (const ulonglong2*)&Ct[wid][0];
            const ulonglong2* c1 = (const ulonglong2*)&Ct[wid + 8][0];
            u64 a0 = 0, a1 = 0;
            #pragma unroll
            for (int q = 0; q < 8; ++q) {
                ulonglong2 g = sc[q];
                scol[q] = g;
                ulonglong2 x0 = c0[q], x1 = c1[q];
                dfma(a0, x0.x, g.x);  dfma(a0, x0.y, g.y);
                dfma(a1, x1.x, g.x);  dfma(a1, x1.y, g.y);
            }
            float s0 = dsum(a0), s1 = dsum(a1);
            CSr[wid][lane] = s0;      CSr[wid + 8][lane] = s1;
            CSc[lane][wid] = s0;      CSc[lane][wid + 8] = s1;
            if (tid < 16) {
                const ulonglong2* c4 = (const ulonglong2*)&Ct[tid][0];
                const ulonglong2* m4 = (const ulonglong2*)muc;
                u64 acc = 0;
                #pragma unroll
                for (int q = 0; q < 8; ++q) {
                    dfma(acc, c4[q].x, m4[q].x);
                    dfma(acc, c4[q].y, m4[q].y);
                }
                rv[tid] = ov[tid] - dsum(acc);
            }
        }
        __syncthreads();

        // ---- P2: S = CS@C^T + 0.03 I; write S out ----
        {
            int i = tid >> 4, j = tid & 15;
            const ulonglong2* a4 = (const ulonglong2*)&CSr[i][0];
            const ulonglong2* c4 = (const ulonglong2*)&Ct[j][0];
            u64 acc = 0;
            #pragma unroll
            for (int q = 0; q < 8; ++q) {
                dfma(acc, a4[q].x, c4[q].x);
                dfma(acc, a4[q].y, c4[q].y);
            }
            float s = ((i == j) ? 0.03f : 0.f) + dsum(acc);
            Ssh[i][j] = s;
            out_S[tb * 256 + tid] = s;
        }
        __syncthreads();

        // ---- P3: warp0 scalar GJ inverse; warps 1-7: U, V, Amu, Dch, R20 ----
        if (wid == 0) {
            const int lrow = lane & 15;
            float M[16];
            const float4* sr = (const float4*)&Ssh[lrow][0];
            #pragma unroll
            for (int q = 0; q < 4; ++q) {
                float4 v = sr[q];
                M[4 * q + 0] = v.x; M[4 * q + 1] = v.y;
                M[4 * q + 2] = v.z; M[4 * q + 3] = v.w;
            }
            #pragma unroll
            for (int j = 0; j < 16; ++j) {
                float pj = __shfl_sync(0xffffffffu, M[j], j);
                float ip;
                asm("rcp.approx.ftz.f32 %0, %1;" : "=f"(ip) : "f"(pj));
                float f  = M[j];
                bool isj = (lrow == j);
                #pragma unroll
                for (int kk = 1; kk < 16; ++kk) {
                    int k = (j + kk) & 15;     // k = j+1 first: shortens pivot chain
                    float rj = __shfl_sync(0xffffffffu, M[k], j);
                    float v  = rj * ip;
                    M[k] = isj ? v : fmaf(-f, v, M[k]);
                }
                M[j] = isj ? ip : (-f * ip);
            }
            if (lane < 16) {
                float4* dst = (float4*)&Sinv[lane][0];
                #pragma unroll
                for (int q = 0; q < 4; ++q)
                    dst[q] = make_float4(M[4 * q], M[4 * q + 1], M[4 * q + 2], M[4 * q + 3]);
            }
        } else {
            int ww   = wid - 1;     // 0..6
            int wtid = tid - 32;    // 0..223
            if (wtid < 16) {
                float4 v = make_float4(0, 0, 0, 0);
                if (wtid >= 8) v = *(const float4*)&chain[t >> 2][(wtid - 8) * 4];
                *(float4*)(out_lm + tb * 64 + wtid * 4) = v;
            }
            if (t + 1 < T_STEPS) {
                // U = A @ sigma (rows ww + 7m), V = A @ W
                ulonglong2 wr[8];
                #pragma unroll
                for (int q = 0; q < 8; ++q)
                    wr[q] = ((const ulonglong2*)&CSr[lane & 15][0])[q];
                #pragma unroll
                for (int m = 0; m < 5; ++m) {
                    int r = ww + 7 * m;
                    if (r < 32) {
                        const ulonglong2* ar = (const ulonglong2*)&Am[r][0];
                        u64 ua = 0, va = 0;
                        #pragma unroll
                        for (int q = 0; q < 8; ++q) {
                            ulonglong2 a = ar[q];
                            dfma(ua, a.x, scol[q].x);  dfma(ua, a.y, scol[q].y);
                            dfma(va, a.x, wr[q].x);    dfma(va, a.y, wr[q].y);
                        }
                        Ush[r][lane] = dsum(ua);
                        Vsh[r][lane & 15] = dsum(va);
                    }
                }
                if (ww == 6) {   // Amu + Dch (warp 7, lightest U load)
                    const ulonglong2* al7 = (const ulonglong2*)&Am[lane][0];
                    const ulonglong2* dl7 = (const ulonglong2*)&Dm[lane][0];
                    const ulonglong2* m4  = (const ulonglong2*)muc;
                    const ulonglong2* ch  = (const ulonglong2*)&chain[t >> 2][0];
                    u64 am = 0, dc = 0;
                    #pragma unroll
                    for (int q = 0; q < 8; ++q) {
                        dfma(am, al7[q].x, m4[q].x);  dfma(am, al7[q].y, m4[q].y);
                        dfma(dc, dl7[q].x, ch[q].x);  dfma(dc, dl7[q].y, ch[q].y);
                    }
                    amv[lane]  = dsum(am);
                    dchv[lane] = dsum(dc);
                }
                if (t < 4) {     // R20 = 20 * D @ D^T
                    ulonglong2 dcol[8];
                    #pragma unroll
                    for (int q = 0; q < 8; ++q)
                        dcol[q] = ((const ulonglong2*)&Dm[lane][0])[q];
                    #pragma unroll
                    for (int m = 0; m < 5; ++m) {
                        int r = ww + 7 * m;
                        if (r < 32) {
                            const ulonglong2* dr = (const ulonglong2*)&Dm[r][0];
                            u64 acc = 0;
                            #pragma unroll
                            for (int q = 0; q < 8; ++q) {
                                dfma(acc, dr[q].x, dcol[q].x);
                                dfma(acc, dr[q].y, dcol[q].y);
                            }
                            Rsh[r][lane] = 20.f * dsum(acc);
                        }
                    }
                }
            }
        }
        __syncthreads();

        // ---- P4: K = W@Sinv, G = V@Sinv (register-carry wl/vl to P5);
        //          al load; t1 rows 0,1; STS next C/obs ----
        ulonglong2 al[8];     // A row `lane` (used for t1)
        ulonglong2 wl[4];     // CSc[lane] — carried to P5 for sigf
        ulonglong2 vl[4];     // Vsh[lane] — carried to P5 for sigma'
        float t1a = 0.f, t1b = 0.f;   // (U A^T)[wid][lane], [wid+8][lane]
        {
            const ulonglong2* i0 = (const ulonglong2*)&Sinv[wid][0];
            const ulonglong2* i1 = (const ulonglong2*)&Sinv[wid + 8][0];
            {
                #pragma unroll
                for (int q = 0; q < 4; ++q) wl[q] = ((const ulonglong2*)&CSc[lane][0])[q];
                u64 a0 = 0, a1 = 0;
                #pragma unroll
                for (int q = 0; q < 4; ++q) {
                    ulonglong2 x = wl[q];
                    dfma(a0, x.x, i0[q].x);  dfma(a0, x.y, i0[q].y);
                    dfma(a1, x.x, i1[q].x);  dfma(a1, x.y, i1[q].y);
                }
                Ksh[lane][wid]     = dsum(a0);
                Ksh[lane][wid + 8] = dsum(a1);
            }
            if (t + 1 < T_STEPS) {
                #pragma unroll
                for (int q = 0; q < 4; ++q) vl[q] = ((const ulonglong2*)&Vsh[lane][0])[q];
                u64 g0 = 0, g1 = 0;
                #pragma unroll
                for (int q = 0; q < 4; ++q) {
                    ulonglong2 x = vl[q];
                    dfma(g0, x.x, i0[q].x);  dfma(g0, x.y, i0[q].y);
                    dfma(g1, x.x, i1[q].x);  dfma(g1, x.y, i1[q].y);
                }
                Gsh[lane][wid]     = dsum(g0);
                Gsh[lane][wid + 8] = dsum(g1);
                #pragma unroll
                for (int q = 0; q < 8; ++q) al[q] = ((const ulonglong2*)&Am[lane][0])[q];
                // t1 rows 0,1 (Ush stable since P3)
                const ulonglong2* u0 = (const ulonglong2*)&Ush[wid][0];
                const ulonglong2* u1 = (const ulonglong2*)&Ush[wid + 8][0];
                u64 ta = 0, tb4 = 0;
                #pragma unroll
                for (int q = 0; q < 8; ++q) {
                    dfma(ta,  u0[q].x, al[q].x);  dfma(ta,  u0[q].y, al[q].y);
                    dfma(tb4, u1[q].x, al[q].x);  dfma(tb4, u1[q].y, al[q].y);
                }
                t1a = dsum(ta);  t1b = dsum(tb4);
                if (tid < 128) *(float4*)&Ct[tid >> 3][(tid & 7) * 4] = rC;
                if (tid < 16)  ov[tid] = rO;
            }
        }
        __syncthreads();

        // ---- P5: sigz -> sigf; sigma' = t1 - G V^T + Q (+R20); mu' ----
        {
            #pragma unroll
            for (int ii = 0; ii < 4; ++ii) {
                int i = wid + 8 * ii;
                const ulonglong2* kr = (const ulonglong2*)&Ksh[i][0];
                u64 acc = 0;
                #pragma unroll
                for (int q = 0; q < 4; ++q) {
                    dfma(acc, kr[q].x, wl[q].x);
                    dfma(acc, kr[q].y, wl[q].y);
                }
                out_sigf[tb * 1024 + i * 32 + lane] = sgc[i][lane] - dsum(acc);
            }
            if (tid < 32) {   // mu_filt
                const ulonglong2* kk = (const ulonglong2*)&Ksh[tid][0];
                const ulonglong2* r4 = (const ulonglong2*)rv;
                u64 acc = 0;
                #pragma unroll
                for (int q = 0; q < 4; ++q) {
                    dfma(acc, kk[q].x, r4[q].x);
                    dfma(acc, kk[q].y, r4[q].y);
                }
                out_muf[tb * 32 + tid] = muc[tid] + dsum(acc);
            }
            if (t + 1 < T_STEPS) {
                const size_t tb2 = tb + BATCH;   // (t+1)*BATCH + b
                // t1 rows 2,3 computed here; rows 0,1 carried from P4
                float t1c, t1d;
                {
                    const ulonglong2* u2 = (const ulonglong2*)&Ush[wid + 16][0];
                    const ulonglong2* u3 = (const ulonglong2*)&Ush[wid + 24][0];
                    u64 tc = 0, td = 0;
                    #pragma unroll
                    for (int q = 0; q < 8; ++q) {
                        dfma(tc, u2[q].x, al[q].x);  dfma(tc, u2[q].y, al[q].y);
                        dfma(td, u3[q].x, al[q].x);  dfma(td, u3[q].y, al[q].y);
                    }
                    t1c = dsum(tc);  t1d = dsum(td);
                }
                float t1v[4] = {t1a, t1b, t1c, t1d};
                #pragma unroll
                for (int ii = 0; ii < 4; ++ii) {
                    int i = wid + 8 * ii;
                    const ulonglong2* gr = (const ulonglong2*)&Gsh[i][0];
                    u64 acc = 0;
                    #pragma unroll
                    for (int q = 0; q < 4; ++q) {
                        dfma(acc, gr[q].x, vl[q].x);
                        dfma(acc, gr[q].y, vl[q].y);
                    }
                    float s = t1v[ii] - dsum(acc);
                    if (i == lane) s += 0.08f;
                    if (t < 4)     s += Rsh[i][lane];
                    sgn[i][lane] = s;
                    out_sigp[tb2 * 1024 + i * 32 + lane] = s;
                }
                if (tid >= 32 && tid < 64) {   // mu' = Amu + G r + Dch
                    int l = lane;
                    const ulonglong2* gr = (const ulonglong2*)&Gsh[l][0];
                    const ulonglong2* r4 = (const ulonglong2*)rv;
                    u64 acc = 0;
                    #pragma unroll
                    for (int q = 0; q < 4; ++q) {
                        dfma(acc, gr[q].x, r4[q].x);
                        dfma(acc, gr[q].y, r4[q].y);
                    }
                    float m = amv[l] + dchv[l] + dsum(acc);
                    mun[l] = m;
                    out_mup[tb2 * 32 + l] = m;
                }
            }
        }
        __syncthreads();
    }
}

extern "C" void kernel_launch(void* const* d_in, const int* in_sizes, int n_in,
                              void* d_out, int out_size) {
    const float* obs = (const float*)d_in[0];
    const float* A   = (const float*)d_in[1];
    const float* C   = (const float*)d_in[2];
    const float* D   = (const float*)d_in[3];
    kalman_kernel<<<BATCH + 20, 256>>>(obs, A, C, D, (float*)d_out);
}